// round 15
// baseline (speedup 1.0000x reference)
#include <cuda_runtime.h>
#include <cuda_bf16.h>
#include <cuda_fp16.h>

// Fused separable 15x15 Gaussian blur, fp32 in/out, N x 1024 x 1024.
// R13 = R12 with TY 128 -> 256: y-halo redundancy 1.055x (was 1.109x).
//  Tile 64(x) x 256(y), 256 threads, grid (16, 4, 16) = 1024 blocks.
//  Phase 1: 4-wide items, 5 predicated LDG.128 direct from global, 60 scalar
//           FMA, fp16 results (uint2 STS). 17 iters x 16 rows = 272 hz rows.
//  Phase 2: 32 strips x 8 rows x 32 col-pairs, 4 serial strips/thread,
//           LDS.32 half2 -> f32x2 FFMA2, fp32 acc.
// smem 34 KB, occ target 5 (48 regs).

#define RAD 7
#define KS  15
#define TX  64
#define TY  256
#define HYP 272                 // 270 needed rows padded to 272 (17 iters x 16 rows)
#define NTHREADS 256
#define IMG_W 1024
#define IMG_H 1024

typedef unsigned long long ull;

__device__ __forceinline__ ull pack2(float a, float b) {
    ull r;
    asm("mov.b64 %0, {%1, %2};" : "=l"(r) : "f"(a), "f"(b));
    return r;
}
__device__ __forceinline__ void unpack2(ull p, float& a, float& b) {
    asm("mov.b64 {%0, %1}, %2;" : "=f"(a), "=f"(b) : "l"(p));
}
__device__ __forceinline__ ull ffma2(ull a, ull b, ull c) {
    ull d;
    asm("fma.rn.f32x2 %0, %1, %2, %3;" : "=l"(d) : "l"(a), "l"(b), "l"(c));
    return d;
}
__device__ __forceinline__ ull fmul2(ull a, ull b) {
    ull d;
    asm("mul.rn.f32x2 %0, %1, %2;" : "=l"(d) : "l"(a), "l"(b));
    return d;
}
// half2 (as u32) -> packed f32x2 in one 64-bit reg
__device__ __forceinline__ ull h2_to_f2(unsigned int h) {
    float lo, hi;
    asm("{.reg .f16 l, h;\n\t"
        " mov.b32 {l, h}, %2;\n\t"
        " cvt.f32.f16 %0, l;\n\t"
        " cvt.f32.f16 %1, h;}"
        : "=f"(lo), "=f"(hi) : "r"(h));
    return pack2(lo, hi);
}

__global__ void __launch_bounds__(NTHREADS, 5)
gauss15_fused13_kernel(const float* __restrict__ x,
                       const float* __restrict__ sigma_p,
                       const float* __restrict__ gain_p,
                       float* __restrict__ out)
{
    __shared__ alignas(16) __half s_hz[HYP * TX];   // 34 KB

    const int tid = threadIdx.x;
    const int x0 = blockIdx.x * TX;
    const int y0 = blockIdx.y * TY;
    const long long plane = (long long)blockIdx.z * (IMG_W * IMG_H);
    const float* img = x + plane;
    float* outp = out + plane;

    // ---- weights: 8 distinct scalars (symmetric) ----
    const float s = fabsf(sigma_p[0]);
    const float g = gain_p[0];
    const float inv2s2 = 1.0f / (2.0f * s * s);
    float ws[8];
#pragma unroll
    for (int j = 0; j < 8; j++) {
        float d = (float)(j - RAD);
        ws[j] = __expf(-d * d * inv2s2);
    }
#define WJ(j) ws[((j) <= 7) ? (j) : (14 - (j))]

    // ---- phase 1: horizontal conv, direct from global ----
    // cg = tid & 15 (invariant; cols x0+4cg..+3), r = (tid>>4) + 16*it, it in [0,17).
    {
        const int cg = tid & 15;
        const int r0 = tid >> 4;
        const int gxb = x0 - 8 + cg * 4;
        const float* rowp0 = img + (long long)(y0 - RAD + r0) * IMG_W + gxb;
        __half* hzp0 = s_hz + r0 * TX + cg * 4;

        bool cvx[5];
#pragma unroll
        for (int k = 0; k < 5; k++) {
            int gx = gxb + 4 * k;
            cvx[k] = (gx >= 0) && (gx < IMG_W);
        }

#pragma unroll 1
        for (int it = 0; it < 17; it++) {
            const int gy = y0 - RAD + (r0 + 16 * it);
            const bool rv = ((unsigned)gy < (unsigned)IMG_H);
            const float* rowp = rowp0 + (long long)(16 * it) * IMG_W;

            float v[20];
#pragma unroll
            for (int k = 0; k < 5; k++) {
                float4 t = make_float4(0.f, 0.f, 0.f, 0.f);
                if (rv && cvx[k]) t = *(const float4*)(rowp + 4 * k);
                v[4 * k + 0] = t.x; v[4 * k + 1] = t.y;
                v[4 * k + 2] = t.z; v[4 * k + 3] = t.w;
            }
            float o0 = 0.f, o1 = 0.f, o2 = 0.f, o3 = 0.f;
#pragma unroll
            for (int j = 0; j < KS; j++) {
                float wj = WJ(j);
                o0 = fmaf(wj, v[1 + j], o0);
                o1 = fmaf(wj, v[2 + j], o1);
                o2 = fmaf(wj, v[3 + j], o2);
                o3 = fmaf(wj, v[4 + j], o3);
            }
            __half2 h01 = __floats2half2_rn(o0, o1);
            __half2 h23 = __floats2half2_rn(o2, o3);
            uint2 st;
            st.x = *(unsigned int*)&h01;
            st.y = *(unsigned int*)&h23;
            *(uint2*)(hzp0 + 16 * it * TX) = st;
        }
    }
    __syncthreads();

    // ---- phase 2: vertical conv, 32 strips x 8 rows x 32 col-pairs ----
    // cp = tid & 31 (cols 2cp, 2cp+1), ss0 = tid >> 5 in [0,8);
    // thread handles strips ss0, ss0+8, ss0+16, ss0+24 serially.
    {
        const int cp = tid & 31;
        const int ss0 = tid >> 5;

        ull wv[8];
#pragma unroll
        for (int j = 0; j < 8; j++) wv[j] = pack2(ws[j], ws[j]);
#define WV(j) wv[((j) <= 7) ? (j) : (14 - (j))]
        const ull gp = pack2(g, g);

#pragma unroll 1
        for (int sit = 0; sit < 4; sit++) {
            const int ob = (ss0 + 8 * sit) * 8;

            ull acc[8];
#pragma unroll
            for (int i = 0; i < 8; i++) acc[i] = 0ull;

            const unsigned int* hzbase =
                (const unsigned int*)(s_hz + ob * TX) + cp;  // half2 units, row stride TX/2
#pragma unroll
            for (int t = 0; t < KS + 7; t++) {               // hz rows ob .. ob+21
                ull v = h2_to_f2(hzbase[t * (TX / 2)]);
#pragma unroll
                for (int k = 0; k < 8; k++) {
                    if (t >= k && t - k < KS)
                        acc[k] = ffma2(WV(t - k), v, acc[k]);
                }
            }

            float* o = outp + (long long)(y0 + ob) * IMG_W + x0 + cp * 2;
#pragma unroll
            for (int k = 0; k < 8; k++) {
                ull r = fmul2(acc[k], gp);
                float a, b;
                unpack2(r, a, b);
                *(float2*)(o + (long long)k * IMG_W) = make_float2(a, b);
            }
        }
    }
}

extern "C" void kernel_launch(void* const* d_in, const int* in_sizes, int n_in,
                              void* d_out, int out_size)
{
    const float* x     = (const float*)d_in[0];
    const float* sigma = (const float*)d_in[1];
    const float* gain  = (const float*)d_in[2];
    float* out = (float*)d_out;

    int nimg = in_sizes[0] / (IMG_W * IMG_H);

    dim3 grid(IMG_W / TX, IMG_H / TY, nimg);
    gauss15_fused13_kernel<<<grid, NTHREADS>>>(x, sigma, gain, out);
}

// round 16
// speedup vs baseline: 1.1362x; 1.1362x over previous
#include <cuda_runtime.h>
#include <cuda_bf16.h>
#include <cuda_fp16.h>

// Fused separable 15x15 Gaussian blur, fp32 in/out, N x 1024 x 1024.
// R14 = R12 (tile 64x128, 256 thr, fp16 hz, 2048 blocks) with ONE change:
//  phase 2 uses a single 16-row strip per thread (8 strips x 32 col-pairs)
//  instead of 2 serial 8-row strips: 30 LDS.32 for 240 FFMA2 (amp 1.875x
//  vs 2.75x). acc[16] -> occ 4.

#define RAD 7
#define KS  15
#define TX  64
#define TY  128
#define HYP 144                 // 142 needed rows padded to 144 (9 iters x 16 rows)
#define NTHREADS 256
#define IMG_W 1024
#define IMG_H 1024

typedef unsigned long long ull;

__device__ __forceinline__ ull pack2(float a, float b) {
    ull r;
    asm("mov.b64 %0, {%1, %2};" : "=l"(r) : "f"(a), "f"(b));
    return r;
}
__device__ __forceinline__ void unpack2(ull p, float& a, float& b) {
    asm("mov.b64 {%0, %1}, %2;" : "=f"(a), "=f"(b) : "l"(p));
}
__device__ __forceinline__ ull ffma2(ull a, ull b, ull c) {
    ull d;
    asm("fma.rn.f32x2 %0, %1, %2, %3;" : "=l"(d) : "l"(a), "l"(b), "l"(c));
    return d;
}
__device__ __forceinline__ ull fmul2(ull a, ull b) {
    ull d;
    asm("mul.rn.f32x2 %0, %1, %2;" : "=l"(d) : "l"(a), "l"(b));
    return d;
}
// half2 (as u32) -> packed f32x2 in one 64-bit reg
__device__ __forceinline__ ull h2_to_f2(unsigned int h) {
    float lo, hi;
    asm("{.reg .f16 l, h;\n\t"
        " mov.b32 {l, h}, %2;\n\t"
        " cvt.f32.f16 %0, l;\n\t"
        " cvt.f32.f16 %1, h;}"
        : "=f"(lo), "=f"(hi) : "r"(h));
    return pack2(lo, hi);
}

__global__ void __launch_bounds__(NTHREADS, 4)
gauss15_fused14_kernel(const float* __restrict__ x,
                       const float* __restrict__ sigma_p,
                       const float* __restrict__ gain_p,
                       float* __restrict__ out)
{
    __shared__ alignas(16) __half s_hz[HYP * TX];   // 18.4 KB

    const int tid = threadIdx.x;
    const int x0 = blockIdx.x * TX;
    const int y0 = blockIdx.y * TY;
    const long long plane = (long long)blockIdx.z * (IMG_W * IMG_H);
    const float* img = x + plane;
    float* outp = out + plane;

    // ---- weights: 8 distinct scalars (symmetric) ----
    const float s = fabsf(sigma_p[0]);
    const float g = gain_p[0];
    const float inv2s2 = 1.0f / (2.0f * s * s);
    float ws[8];
#pragma unroll
    for (int j = 0; j < 8; j++) {
        float d = (float)(j - RAD);
        ws[j] = __expf(-d * d * inv2s2);
    }
#define WJ(j) ws[((j) <= 7) ? (j) : (14 - (j))]

    // ---- phase 1: horizontal conv, direct from global (R12 verbatim) ----
    // cg = tid & 15 (invariant; cols x0+4cg..+3), r = (tid>>4) + 16*it, it in [0,9).
    {
        const int cg = tid & 15;
        const int r0 = tid >> 4;
        const int gxb = x0 - 8 + cg * 4;
        const float* rowp0 = img + (long long)(y0 - RAD + r0) * IMG_W + gxb;
        __half* hzp0 = s_hz + r0 * TX + cg * 4;

        bool cvx[5];
#pragma unroll
        for (int k = 0; k < 5; k++) {
            int gx = gxb + 4 * k;
            cvx[k] = (gx >= 0) && (gx < IMG_W);
        }

#pragma unroll
        for (int it = 0; it < 9; it++) {
            const int gy = y0 - RAD + (r0 + 16 * it);
            const bool rv = ((unsigned)gy < (unsigned)IMG_H);
            const float* rowp = rowp0 + (long long)(16 * it) * IMG_W;

            float v[20];
#pragma unroll
            for (int k = 0; k < 5; k++) {
                float4 t = make_float4(0.f, 0.f, 0.f, 0.f);
                if (rv && cvx[k]) t = *(const float4*)(rowp + 4 * k);
                v[4 * k + 0] = t.x; v[4 * k + 1] = t.y;
                v[4 * k + 2] = t.z; v[4 * k + 3] = t.w;
            }
            float o0 = 0.f, o1 = 0.f, o2 = 0.f, o3 = 0.f;
#pragma unroll
            for (int j = 0; j < KS; j++) {
                float wj = WJ(j);
                o0 = fmaf(wj, v[1 + j], o0);
                o1 = fmaf(wj, v[2 + j], o1);
                o2 = fmaf(wj, v[3 + j], o2);
                o3 = fmaf(wj, v[4 + j], o3);
            }
            __half2 h01 = __floats2half2_rn(o0, o1);
            __half2 h23 = __floats2half2_rn(o2, o3);
            uint2 st;
            st.x = *(unsigned int*)&h01;
            st.y = *(unsigned int*)&h23;
            *(uint2*)(hzp0 + 16 * it * TX) = st;
        }
    }
    __syncthreads();

    // ---- phase 2: vertical conv, 8 strips x 16 rows x 32 col-pairs ----
    // cp = tid & 31 (cols 2cp, 2cp+1), ss = tid >> 5 in [0,8), ob = 16*ss.
    // 30 LDS.32 per thread feed 16 packed accumulators (240 FFMA2).
    {
        const int cp = tid & 31;
        const int ss = tid >> 5;
        const int ob = ss * 16;

        ull wv[8];
#pragma unroll
        for (int j = 0; j < 8; j++) wv[j] = pack2(ws[j], ws[j]);
#define WV(j) wv[((j) <= 7) ? (j) : (14 - (j))]
        const ull gp = pack2(g, g);

        ull acc[16];
#pragma unroll
        for (int i = 0; i < 16; i++) acc[i] = 0ull;

        const unsigned int* hzbase =
            (const unsigned int*)(s_hz + ob * TX) + cp;   // half2 units, row stride TX/2
#pragma unroll
        for (int t = 0; t < KS + 15; t++) {               // hz rows ob .. ob+29
            ull v = h2_to_f2(hzbase[t * (TX / 2)]);
#pragma unroll
            for (int k = 0; k < 16; k++) {
                if (t >= k && t - k < KS)
                    acc[k] = ffma2(WV(t - k), v, acc[k]);
            }
        }

        float* o = outp + (long long)(y0 + ob) * IMG_W + x0 + cp * 2;
#pragma unroll
        for (int k = 0; k < 16; k++) {
            ull r = fmul2(acc[k], gp);
            float a, b;
            unpack2(r, a, b);
            *(float2*)(o + (long long)k * IMG_W) = make_float2(a, b);
        }
    }
}

extern "C" void kernel_launch(void* const* d_in, const int* in_sizes, int n_in,
                              void* d_out, int out_size)
{
    const float* x     = (const float*)d_in[0];
    const float* sigma = (const float*)d_in[1];
    const float* gain  = (const float*)d_in[2];
    float* out = (float*)d_out;

    int nimg = in_sizes[0] / (IMG_W * IMG_H);

    dim3 grid(IMG_W / TX, IMG_H / TY, nimg);
    gauss15_fused14_kernel<<<grid, NTHREADS>>>(x, sigma, gain, out);
}